// round 8
// baseline (speedup 1.0000x reference)
#include <cuda_runtime.h>

#define NB      32
#define NIN     1034
#define NOUT    512
#define STRIDE  1088
#define KNS     1000.0f
#define MINW    (-0.3678794411714423f)
#define EF      2.718281828459045f
#define NBUCK   2048
#define OPW     4          // output neurons per warp

// packed per-batch sorted data: (t, e^t, t*e^t, idx-as-int-bits)
__device__ float4 g_pack[NB * STRIDE];

__device__ __forceinline__ float get_t(const float* __restrict__ x,
                                       const float* __restrict__ pulse,
                                       int b, int i) {
    return (i < 1024) ? x[b * 1024 + i] : pulse[i - 1024];
}

__device__ __forceinline__ int bucket_of(float t) {
    int bid = (int)(t * (float)NBUCK);
    return bid < 0 ? 0 : (bid >= NBUCK ? NBUCK - 1 : bid);
}

// ---------------------------------------------------------------------------
// Kernel 1: per-batch bucket sort + pack.  grid=NB, block=1024.
// ---------------------------------------------------------------------------
__global__ void sort_pack_kernel(const float* __restrict__ x,
                                 const float* __restrict__ pulse) {
    __shared__ int cnt [NBUCK];
    __shared__ int base[NBUCK];
    __shared__ unsigned long long keys[NIN];
    __shared__ float wsum[32];

    const int b   = blockIdx.x;
    const int tid = threadIdx.x;
    const int lane = tid & 31, wid = tid >> 5;

    cnt[tid] = 0; cnt[tid + 1024] = 0;
    __syncthreads();

    for (int i = tid; i < NIN; i += 1024) {
        const float t = get_t(x, pulse, b, i);
        atomicAdd(&cnt[bucket_of(t)], 1);
    }
    __syncthreads();

    {
        const int v0 = cnt[2 * tid], v1 = cnt[2 * tid + 1];
        float s = (float)(v0 + v1);
        #pragma unroll
        for (int off = 1; off < 32; off <<= 1) {
            const float u = __shfl_up_sync(0xffffffffu, s, off);
            if (lane >= off) s += u;
        }
        if (lane == 31) wsum[wid] = s;
        __syncthreads();
        if (wid == 0) {
            float ws = wsum[lane];
            #pragma unroll
            for (int off = 1; off < 32; off <<= 1) {
                const float u = __shfl_up_sync(0xffffffffu, ws, off);
                if (lane >= off) ws += u;
            }
            wsum[lane] = ws;
        }
        __syncthreads();
        const int incl = (int)s + (wid ? (int)wsum[wid - 1] : 0);
        const int excl = incl - v0 - v1;
        base[2 * tid]     = excl;
        base[2 * tid + 1] = excl + v0;
        __syncthreads();
        cnt[2 * tid]     = excl;
        cnt[2 * tid + 1] = excl + v0;
    }
    __syncthreads();

    for (int i = tid; i < NIN; i += 1024) {
        const float t = get_t(x, pulse, b, i);
        const int pos = atomicAdd(&cnt[bucket_of(t)], 1);
        keys[pos] = ((unsigned long long)__float_as_uint(t) << 32) | (unsigned)i;
    }
    __syncthreads();

    for (int bk = tid; bk < NBUCK; bk += 1024) {
        const int s0 = base[bk];
        const int s1 = (bk + 1 < NBUCK) ? base[bk + 1] : NIN;
        for (int i = s0 + 1; i < s1; ++i) {
            const unsigned long long v = keys[i];
            int j = i - 1;
            while (j >= s0 && keys[j] > v) { keys[j + 1] = keys[j]; --j; }
            keys[j + 1] = v;
        }
    }
    __syncthreads();

    for (int i = tid; i < STRIDE; i += 1024) {
        if (i < NIN) {
            const unsigned long long v = keys[i];
            const float t = __uint_as_float((unsigned)(v >> 32));
            const int idx = (int)(unsigned)v;
            const float z = expf(t);
            g_pack[b * STRIDE + i] = make_float4(t, z, z * t, __int_as_float(idx));
        } else {
            g_pack[b * STRIDE + i] = make_float4(KNS, 0.0f, 0.0f, 0.0f);
        }
    }
}

// packed f32x2 helpers (Blackwell)
__device__ __forceinline__ unsigned long long pack2(float lo, float hi) {
    unsigned long long r;
    asm("mov.b64 %0, {%1, %2};" : "=l"(r) : "f"(lo), "f"(hi));
    return r;
}
__device__ __forceinline__ void unpack2(unsigned long long v, float& lo, float& hi) {
    asm("mov.b64 {%0, %1}, %2;" : "=f"(lo), "=f"(hi) : "l"(v));
}
__device__ __forceinline__ unsigned long long addf32x2(unsigned long long a,
                                                       unsigned long long b) {
    unsigned long long r;
    asm("add.rn.f32x2 %0, %1, %2;" : "=l"(r) : "l"(a), "l"(b));
    return r;
}

// ---------------------------------------------------------------------------
// Kernel 2: one warp per (batch, 4 output neurons). Four interleaved packed
// scans (ILP hides shfl latency); analytic window tests; Lambert W deferred
// to a single post-loop pass on lanes 0..3.
// ---------------------------------------------------------------------------
__global__ void solve_kernel(const float* __restrict__ W,
                             float* __restrict__ out) {
    const int gw   = (int)((blockIdx.x * blockDim.x + threadIdx.x) >> 5);
    const int lane = threadIdx.x & 31;
    const int b    = gw >> 7;                 // / (NOUT/OPW)
    const int o0   = (gw & 127) * OPW;

    const float4* __restrict__ pk = g_pack + b * STRIDE;
    const float* __restrict__ wr[OPW] = {
        W + (o0 + 0) * NIN, W + (o0 + 1) * NIN,
        W + (o0 + 2) * NIN, W + (o0 + 3) * NIN };

    unsigned long long carry[OPW] = {0ull, 0ull, 0ull, 0ull};
    float winA[OPW], winB[OPW];
    unsigned spiked = 0;                      // warp-uniform bitmask

    for (int k0 = 0; k0 < NIN && spiked != 0xF; k0 += 32) {
        const int k = k0 + lane;
        const float4 p = pk[k];
        const float t  = p.x;
        const float z  = p.y;
        const float zt = p.z;
        const int  idx = __float_as_int(p.w);

        // next (t, z): one packed shfl; lane 31 reads next chunk head
        unsigned long long ntz = __shfl_down_sync(0xffffffffu, pack2(t, z), 1);
        float nt, nz;
        unpack2(ntz, nt, nz);
        if (lane == 31) { const float4 q = pk[k0 + 32]; nt = q.x; nz = q.y; }

        // four independent packed (A,B) scans, interleaved for ILP
        unsigned long long ab[OPW];
        #pragma unroll
        for (int j = 0; j < OPW; ++j) {
            const float w = wr[j][idx];
            ab[j] = pack2(w * z, w * zt);
        }
        #pragma unroll
        for (int off = 1; off < 32; off <<= 1) {
            unsigned long long u[OPW];
            #pragma unroll
            for (int j = 0; j < OPW; ++j)
                u[j] = __shfl_up_sync(0xffffffffu, ab[j], off);
            if (lane >= off) {
                #pragma unroll
                for (int j = 0; j < OPW; ++j)
                    ab[j] = addf32x2(ab[j], u[j]);
            }
        }

        #pragma unroll
        for (int j = 0; j < OPW; ++j) {
            const unsigned long long tot = __shfl_sync(0xffffffffu, ab[j], 31);
            const unsigned long long cum = addf32x2(carry[j], ab[j]);
            float A, B;
            unpack2(cum, A, B);

            bool valid = false;
            if (A > 1e-10f) {
                const float lnA = __logf(A);
                const float boa = __fdividef(B, A);
                const bool reach = lnA >= boa + 1.0f;        // arg >= -1/e
                const bool lower = fmaf(A, t,  -B) <= z;     // t* >= t_k
                const bool upper = (nt >= lnA) ||
                                   (fmaf(A, nt, -B) >= nz);  // t* <= t_{k+1}
                valid = reach && lower && upper && (t < KNS);
            }
            const unsigned vm = __ballot_sync(0xffffffffu, valid);
            if (vm && !(spiked & (1u << j))) {
                const int src = __ffs((int)vm) - 1;
                winA[j] = __shfl_sync(0xffffffffu, A, src);
                winB[j] = __shfl_sync(0xffffffffu, B, src);
                spiked |= (1u << j);
            }
            carry[j] = addf32x2(carry[j], tot);
        }
    }

    // deferred Lambert: lanes 0..3 solve the four winners in parallel
    float tc = KNS;
    if (lane < OPW) {
        const float A = (lane == 0) ? winA[0] : (lane == 1) ? winA[1]
                      : (lane == 2) ? winA[2] : winA[3];
        const float B = (lane == 0) ? winB[0] : (lane == 1) ? winB[1]
                      : (lane == 2) ? winB[2] : winB[3];
        if ((spiked >> lane) & 1u) {
            const float boa = B / A;
            float xw = -1.0f / A * expf(fminf(boa, 80.0f));
            xw = fmaxf(fminf(xw, 0.0f), MINW);
            float wv;
            if (xw < -0.25f) {
                const float pbr = sqrtf(fmaxf(2.0f * (1.0f + EF * xw), 0.0f));
                wv = -1.0f + pbr * (1.0f + pbr * (-0.33333333f + pbr * 0.15277778f));
            } else {
                wv = xw * (1.0f - xw * (1.0f - 1.5f * xw));
            }
            #pragma unroll
            for (int it = 0; it < 3; ++it) {
                const float ew = expf(wv);
                const float f  = wv * ew - xw;
                const float denom = ew * (wv + 1.0f)
                          - (wv + 2.0f) * f / (2.0f * (wv + 1.0f) + 1e-12f);
                wv = wv - f / (denom + 1e-12f);
            }
            tc = boa - wv;
        }
        out[b * NOUT + o0 + lane] = tc;
    }
}

// ---------------------------------------------------------------------------
extern "C" void kernel_launch(void* const* d_in, const int* in_sizes, int n_in,
                              void* d_out, int out_size) {
    const float* x      = (const float*)d_in[0];   // [32, 1024]
    const float* weight = (const float*)d_in[1];   // [512, 1034]
    const float* pulse  = (const float*)d_in[2];   // [10]
    float* out = (float*)d_out;                    // [32, 512]

    sort_pack_kernel<<<NB, 1024>>>(x, pulse);

    const int warps = NB * NOUT / OPW;             // 4096 warps
    solve_kernel<<<warps / 8, 256>>>(weight, out);
}

// round 9
// speedup vs baseline: 1.3876x; 1.3876x over previous
#include <cuda_runtime.h>

#define NB      32
#define NIN     1034
#define NOUT    512
#define STRIDE  1088
#define KNS     1000.0f
#define MINW    (-0.3678794411714423f)
#define EF      2.718281828459045f
#define NBUCK   2048
#define OPW     2          // output neurons per warp

// packed per-batch sorted data: (t, e^t, t*e^t, idx-as-int-bits)
__device__ float4 g_pack[NB * STRIDE];

__device__ __forceinline__ float get_t(const float* __restrict__ x,
                                       const float* __restrict__ pulse,
                                       int b, int i) {
    return (i < 1024) ? x[b * 1024 + i] : pulse[i - 1024];
}

__device__ __forceinline__ int bucket_of(float t) {
    int bid = (int)(t * (float)NBUCK);
    return bid < 0 ? 0 : (bid >= NBUCK ? NBUCK - 1 : bid);
}

// ---------------------------------------------------------------------------
// Kernel 1: per-batch bucket sort + pack.  grid=NB, block=1024.
// ---------------------------------------------------------------------------
__global__ void sort_pack_kernel(const float* __restrict__ x,
                                 const float* __restrict__ pulse) {
    __shared__ int cnt [NBUCK];
    __shared__ int base[NBUCK];
    __shared__ unsigned long long keys[NIN];
    __shared__ float wsum[32];

    const int b   = blockIdx.x;
    const int tid = threadIdx.x;
    const int lane = tid & 31, wid = tid >> 5;

    cnt[tid] = 0; cnt[tid + 1024] = 0;
    __syncthreads();

    for (int i = tid; i < NIN; i += 1024) {
        const float t = get_t(x, pulse, b, i);
        atomicAdd(&cnt[bucket_of(t)], 1);
    }
    __syncthreads();

    {
        const int v0 = cnt[2 * tid], v1 = cnt[2 * tid + 1];
        float s = (float)(v0 + v1);
        #pragma unroll
        for (int off = 1; off < 32; off <<= 1) {
            const float u = __shfl_up_sync(0xffffffffu, s, off);
            if (lane >= off) s += u;
        }
        if (lane == 31) wsum[wid] = s;
        __syncthreads();
        if (wid == 0) {
            float ws = wsum[lane];
            #pragma unroll
            for (int off = 1; off < 32; off <<= 1) {
                const float u = __shfl_up_sync(0xffffffffu, ws, off);
                if (lane >= off) ws += u;
            }
            wsum[lane] = ws;
        }
        __syncthreads();
        const int incl = (int)s + (wid ? (int)wsum[wid - 1] : 0);
        const int excl = incl - v0 - v1;
        base[2 * tid]     = excl;
        base[2 * tid + 1] = excl + v0;
        __syncthreads();
        cnt[2 * tid]     = excl;
        cnt[2 * tid + 1] = excl + v0;
    }
    __syncthreads();

    for (int i = tid; i < NIN; i += 1024) {
        const float t = get_t(x, pulse, b, i);
        const int pos = atomicAdd(&cnt[bucket_of(t)], 1);
        keys[pos] = ((unsigned long long)__float_as_uint(t) << 32) | (unsigned)i;
    }
    __syncthreads();

    for (int bk = tid; bk < NBUCK; bk += 1024) {
        const int s0 = base[bk];
        const int s1 = (bk + 1 < NBUCK) ? base[bk + 1] : NIN;
        for (int i = s0 + 1; i < s1; ++i) {
            const unsigned long long v = keys[i];
            int j = i - 1;
            while (j >= s0 && keys[j] > v) { keys[j + 1] = keys[j]; --j; }
            keys[j + 1] = v;
        }
    }
    __syncthreads();

    for (int i = tid; i < STRIDE; i += 1024) {
        if (i < NIN) {
            const unsigned long long v = keys[i];
            const float t = __uint_as_float((unsigned)(v >> 32));
            const int idx = (int)(unsigned)v;
            const float z = expf(t);
            g_pack[b * STRIDE + i] = make_float4(t, z, z * t, __int_as_float(idx));
        } else {
            g_pack[b * STRIDE + i] = make_float4(KNS, 0.0f, 0.0f, 0.0f);
        }
    }
}

// packed f32x2 helpers (Blackwell)
__device__ __forceinline__ unsigned long long pack2(float lo, float hi) {
    unsigned long long r;
    asm("mov.b64 %0, {%1, %2};" : "=l"(r) : "f"(lo), "f"(hi));
    return r;
}
__device__ __forceinline__ void unpack2(unsigned long long v, float& lo, float& hi) {
    asm("mov.b64 {%0, %1}, %2;" : "=f"(lo), "=f"(hi) : "l"(v));
}
__device__ __forceinline__ unsigned long long addf32x2(unsigned long long a,
                                                       unsigned long long b) {
    unsigned long long r;
    asm("add.rn.f32x2 %0, %1, %2;" : "=l"(r) : "l"(a), "l"(b));
    return r;
}

// ---------------------------------------------------------------------------
// Kernel 2: one warp per (batch, 2 output neurons). Two interleaved packed
// scans (ILP on the shfl chain) at full one-wave occupancy; analytic window
// tests; Lambert W deferred to a single post-loop pass on lanes 0..1.
// ---------------------------------------------------------------------------
__global__ void __launch_bounds__(128, 16)
solve_kernel(const float* __restrict__ W, float* __restrict__ out) {
    const int gw   = (int)((blockIdx.x * blockDim.x + threadIdx.x) >> 5);
    const int lane = threadIdx.x & 31;
    const int b    = gw >> 8;                 // / (NOUT/OPW)
    const int o0   = (gw & 255) * OPW;

    const float4* __restrict__ pk = g_pack + b * STRIDE;
    const float* __restrict__ wr0 = W + (o0 + 0) * NIN;
    const float* __restrict__ wr1 = W + (o0 + 1) * NIN;

    unsigned long long carry0 = 0ull, carry1 = 0ull;
    float winA[OPW], winB[OPW];
    unsigned spiked = 0;                      // warp-uniform bitmask

    for (int k0 = 0; k0 < NIN && spiked != 0x3; k0 += 32) {
        const int k = k0 + lane;
        const float4 p = pk[k];
        const float t  = p.x;
        const float z  = p.y;
        const float zt = p.z;
        const int  idx = __float_as_int(p.w);

        // next (t, z): one packed shfl; lane 31 reads next chunk head
        unsigned long long ntz = __shfl_down_sync(0xffffffffu, pack2(t, z), 1);
        float nt, nz;
        unpack2(ntz, nt, nz);
        if (lane == 31) { const float4 q = pk[k0 + 32]; nt = q.x; nz = q.y; }

        // two independent packed (A,B) scans, interleaved for ILP
        const float w0 = wr0[idx];
        const float w1 = wr1[idx];
        unsigned long long ab0 = pack2(w0 * z, w0 * zt);
        unsigned long long ab1 = pack2(w1 * z, w1 * zt);
        #pragma unroll
        for (int off = 1; off < 32; off <<= 1) {
            const unsigned long long u0 = __shfl_up_sync(0xffffffffu, ab0, off);
            const unsigned long long u1 = __shfl_up_sync(0xffffffffu, ab1, off);
            if (lane >= off) {
                ab0 = addf32x2(ab0, u0);
                ab1 = addf32x2(ab1, u1);
            }
        }
        const unsigned long long tot0 = __shfl_sync(0xffffffffu, ab0, 31);
        const unsigned long long tot1 = __shfl_sync(0xffffffffu, ab1, 31);
        const unsigned long long cum0 = addf32x2(carry0, ab0);
        const unsigned long long cum1 = addf32x2(carry1, ab1);

        float A0, B0, A1, B1;
        unpack2(cum0, A0, B0);
        unpack2(cum1, A1, B1);

        // window tests for both outputs (independent, interleaved by compiler)
        bool v0 = false, v1 = false;
        if (A0 > 1e-10f) {
            const float lnA = __logf(A0);
            const float boa = __fdividef(B0, A0);
            v0 = (lnA >= boa + 1.0f)
               && (fmaf(A0, t, -B0) <= z)
               && ((nt >= lnA) || (fmaf(A0, nt, -B0) >= nz))
               && (t < KNS);
        }
        if (A1 > 1e-10f) {
            const float lnA = __logf(A1);
            const float boa = __fdividef(B1, A1);
            v1 = (lnA >= boa + 1.0f)
               && (fmaf(A1, t, -B1) <= z)
               && ((nt >= lnA) || (fmaf(A1, nt, -B1) >= nz))
               && (t < KNS);
        }
        const unsigned m0 = __ballot_sync(0xffffffffu, v0);
        const unsigned m1 = __ballot_sync(0xffffffffu, v1);
        if (m0 && !(spiked & 1u)) {
            const int src = __ffs((int)m0) - 1;
            winA[0] = __shfl_sync(0xffffffffu, A0, src);
            winB[0] = __shfl_sync(0xffffffffu, B0, src);
            spiked |= 1u;
        }
        if (m1 && !(spiked & 2u)) {
            const int src = __ffs((int)m1) - 1;
            winA[1] = __shfl_sync(0xffffffffu, A1, src);
            winB[1] = __shfl_sync(0xffffffffu, B1, src);
            spiked |= 2u;
        }
        carry0 = addf32x2(carry0, tot0);
        carry1 = addf32x2(carry1, tot1);
    }

    // deferred Lambert: lanes 0..1 solve the two winners in parallel
    float tc = KNS;
    if (lane < OPW) {
        const float A = (lane == 0) ? winA[0] : winA[1];
        const float B = (lane == 0) ? winB[0] : winB[1];
        if ((spiked >> lane) & 1u) {
            const float boa = B / A;
            float xw = -1.0f / A * expf(fminf(boa, 80.0f));
            xw = fmaxf(fminf(xw, 0.0f), MINW);
            float wv;
            if (xw < -0.25f) {
                const float pbr = sqrtf(fmaxf(2.0f * (1.0f + EF * xw), 0.0f));
                wv = -1.0f + pbr * (1.0f + pbr * (-0.33333333f + pbr * 0.15277778f));
            } else {
                wv = xw * (1.0f - xw * (1.0f - 1.5f * xw));
            }
            #pragma unroll
            for (int it = 0; it < 3; ++it) {
                const float ew = expf(wv);
                const float f  = wv * ew - xw;
                const float denom = ew * (wv + 1.0f)
                          - (wv + 2.0f) * f / (2.0f * (wv + 1.0f) + 1e-12f);
                wv = wv - f / (denom + 1e-12f);
            }
            tc = boa - wv;
        }
        out[b * NOUT + o0 + lane] = tc;
    }
}

// ---------------------------------------------------------------------------
extern "C" void kernel_launch(void* const* d_in, const int* in_sizes, int n_in,
                              void* d_out, int out_size) {
    const float* x      = (const float*)d_in[0];   // [32, 1024]
    const float* weight = (const float*)d_in[1];   // [512, 1034]
    const float* pulse  = (const float*)d_in[2];   // [10]
    float* out = (float*)d_out;                    // [32, 512]

    sort_pack_kernel<<<NB, 1024>>>(x, pulse);

    // one warp per (b, 2 outputs): 8192 warps, 128-thr blocks -> 2048 blocks
    const int warps = NB * NOUT / OPW;
    solve_kernel<<<warps / 4, 128>>>(weight, out);
}